// round 6
// baseline (speedup 1.0000x reference)
#include <cuda_runtime.h>
#include <cuda_bf16.h>
#include <cstdint>

// ---------------- problem constants ----------------
#define B_    16
#define CIN   512
#define COUT  256
#define H_    56
#define W_    56
#define HO    28
#define WO    28
#define NPB   784
#define NTOT  (B_ * NPB)      // 12544
#define HW    (H_ * W_)       // 3136
#define CH    16              // k per chunk
#define NCHK  (CIN / CH)      // 32
#define BN    32
#define BM    256

// preconverted W, chunk-major: [chunk j][m][ hi k0..15 | lo k0..15 ]  (512 KB)
__device__ __align__(16) __nv_bfloat16 g_wf[NCHK * COUT * 32];

// ---- smem layout (bytes) ----
#define A_STAGE 20480         // 256 rows x 80B (hi 2x16B | lo 2x16B, 16B pad)
#define A_OFF   0             // 3 stages = 61440
#define X_STAGE 8192          // 16 ch x 16 pairs x 32B
#define X_OFF   61440         // 3 stages = 24576
#define B_OFF   86016         // 2 x 2KB (16 rows x 128B: hi|lo swizzled)
#define S_OFF   90112         // s_sc[512] + s_sh[512]
#define SMEM_TOT 94208

__device__ __forceinline__ uint32_t smem_u32(const void* p) {
    uint32_t a;
    asm("{ .reg .u64 t; cvta.to.shared.u64 t, %1; cvt.u32.u64 %0, t; }" : "=r"(a) : "l"(p));
    return a;
}
#define CP_ASYNC16(dst_u32, src_ptr) \
    asm volatile("cp.async.cg.shared.global [%0], [%1], 16;" :: "r"(dst_u32), "l"(src_ptr))
#define CP_COMMIT() asm volatile("cp.async.commit_group;")
#define CP_WAIT1()  asm volatile("cp.async.wait_group 1;")

#define LDSM4(R0, R1, R2, R3, A) \
    asm volatile("ldmatrix.sync.aligned.m8n8.x4.shared.b16 {%0,%1,%2,%3}, [%4];" \
                 : "=r"(R0), "=r"(R1), "=r"(R2), "=r"(R3) : "r"(A))
#define LDSM4T(R0, R1, R2, R3, A) \
    asm volatile("ldmatrix.sync.aligned.m8n8.x4.trans.shared.b16 {%0,%1,%2,%3}, [%4];" \
                 : "=r"(R0), "=r"(R1), "=r"(R2), "=r"(R3) : "r"(A))
#define MMA16816(C, A0, A1, A2, A3, B0, B1) \
    asm volatile("mma.sync.aligned.m16n8k16.row.col.f32.bf16.bf16.f32 " \
                 "{%0,%1,%2,%3}, {%4,%5,%6,%7}, {%8,%9}, {%0,%1,%2,%3};" \
                 : "+f"((C)[0]), "+f"((C)[1]), "+f"((C)[2]), "+f"((C)[3]) \
                 : "r"(A0), "r"(A1), "r"(A2), "r"(A3), "r"(B0), "r"(B1))

// ============================================================================
// Kernel 0: W fp32 -> bf16 hi/lo, chunk-major layout
// ============================================================================
__global__ void prep_w(const float* __restrict__ w) {
    int i = blockIdx.x * 512 + threadIdx.x;     // < 131072
    int m = i >> 9, k = i & 511;
    float v = w[i];
    __nv_bfloat16 hi = __float2bfloat16(v);
    __nv_bfloat16 lo = __float2bfloat16(v - __bfloat162float(hi));
    size_t base = (size_t)(k >> 4) * (COUT * 32) + m * 32 + (k & 15);
    g_wf[base]      = hi;
    g_wf[base + 16] = lo;
}

// ============================================================================
// Fused: BN+ReLU+pool (x via 3-stage cp.async) + A via cp.async + bf16x3 MMA
// ============================================================================
__global__ __launch_bounds__(256, 2)
void fused_all(const float* __restrict__ x,
               const float* __restrict__ gamma,
               const float* __restrict__ beta,
               const float* __restrict__ mean,
               const float* __restrict__ var,
               float* __restrict__ out) {
    extern __shared__ char sm[];
    const uint32_t sb = smem_u32(sm);
    const int tid = threadIdx.x;
    const int lid = tid & 31, wid = tid >> 5;
    const int n0 = blockIdx.x * BN;

    float* s_sc = (float*)(sm + S_OFF);
    float* s_sh = s_sc + 512;

    // ---- BN constants ----
    {
        int c = tid;
        float sc = gamma[c] * rsqrtf(var[c] + 1e-5f);
        s_sc[c] = sc;  s_sh[c] = beta[c] - mean[c] * sc;
        c += 256;
        sc = gamma[c] * rsqrtf(var[c] + 1e-5f);
        s_sc[c] = sc;  s_sh[c] = beta[c] - mean[c] * sc;
    }

    // ---- x producer mapping: thread owns (channel cgq, n-pair pr) ----
    const int pr  = tid & 15;
    const int cgq = tid >> 4;            // 0..15
    const int nn = n0 + 2 * pr;
    const int bb = nn / NPB;
    const int pp = nn - bb * NPB;
    const int ho = pp / WO, wo = pp - ho * WO;   // wo even
    const float* xb = x + ((size_t)bb * CIN * H_ + 2 * ho) * W_ + 2 * wo;

    // ---- cp.async issue for chunk j -> slot j%3 ----
    auto issue = [&](int j) {
        const int slot = j % 3;
        // A: thread = m row, 4x16B, coalesced from chunk-major g_wf
        {
            uint32_t dst = sb + A_OFF + slot * A_STAGE + tid * 80;
            const __nv_bfloat16* src = g_wf + (size_t)j * (COUT * 32) + tid * 32;
            CP_ASYNC16(dst,      src);
            CP_ASYNC16(dst + 16, src + 8);
            CP_ASYNC16(dst + 32, src + 16);
            CP_ASYNC16(dst + 48, src + 24);
        }
        // x raw: (cgq, pr) 2 rows of 16B
        {
            uint32_t dst = sb + X_OFF + slot * X_STAGE + cgq * 512 + pr * 32;
            const float* src = xb + (size_t)(j * CH + cgq) * HW;
            CP_ASYNC16(dst,      src);
            CP_ASYNC16(dst + 16, src + W_);
        }
    };

    // ---- pool chunk i from raw smem -> B[i&1] ----
    auto pool = [&](int i) {
        const int slot = i % 3;
        const float* raw = (const float*)(sm + X_OFF + slot * X_STAGE + cgq * 512 + pr * 32);
        float4 r0 = *(const float4*)raw;
        float4 r1 = *(const float4*)(raw + 4);
        float sc = s_sc[i * CH + cgq], sh = s_sh[i * CH + cgq];
        float v0 = fmaxf(fmaf(r0.x, sc, sh), 0.f) + fmaxf(fmaf(r0.y, sc, sh), 0.f)
                 + fmaxf(fmaf(r1.x, sc, sh), 0.f) + fmaxf(fmaf(r1.y, sc, sh), 0.f);
        float v1 = fmaxf(fmaf(r0.z, sc, sh), 0.f) + fmaxf(fmaf(r0.w, sc, sh), 0.f)
                 + fmaxf(fmaf(r1.z, sc, sh), 0.f) + fmaxf(fmaf(r1.w, sc, sh), 0.f);
        v0 *= 0.25f; v1 *= 0.25f;
        __nv_bfloat16 h0 = __float2bfloat16(v0), h1 = __float2bfloat16(v1);
        __nv_bfloat16 e0 = __float2bfloat16(v0 - __bfloat162float(h0));
        __nv_bfloat16 e1 = __float2bfloat16(v1 - __bfloat162float(h1));
        uint32_t hp = ((uint32_t)__bfloat16_as_ushort(h1) << 16) | __bfloat16_as_ushort(h0);
        uint32_t lp = ((uint32_t)__bfloat16_as_ushort(e1) << 16) | __bfloat16_as_ushort(e0);
        char* bbase = sm + B_OFF + (size_t)(i & 1) * 2048;
        const uint32_t sub = (uint32_t)(pr & 3) * 4;
        const uint32_t uhi = (uint32_t)(pr >> 2);
        uint32_t rb = (uint32_t)cgq * 128;
        *(uint32_t*)(bbase + rb + ((uhi       ^ (uint32_t)(cgq & 7)) * 16) + sub) = hp;
        *(uint32_t*)(bbase + rb + (((uhi | 4) ^ (uint32_t)(cgq & 7)) * 16) + sub) = lp;
    };

    const int half = lid >> 4;
    float acc[2][4][4];
#pragma unroll
    for (int a = 0; a < 2; a++)
#pragma unroll
        for (int b = 0; b < 4; b++)
#pragma unroll
            for (int c = 0; c < 4; c++) acc[a][b][c] = 0.f;

    // ---- MMA on chunk i ----
    auto mma = [&](int i) {
        const uint32_t abuf = sb + A_OFF + (uint32_t)(i % 3) * A_STAGE;
        const uint32_t bbuf = sb + B_OFF + (uint32_t)(i & 1) * 2048;
        const int rk = lid & 15;
        const uint32_t brow = bbuf + (uint32_t)rk * 128;
        uint32_t bh[8], bl[8];
#pragma unroll
        for (int q = 0; q < 2; q++) {
            uint32_t u = (uint32_t)(2 * q + half);
            LDSM4T(bh[q*4+0], bh[q*4+1], bh[q*4+2], bh[q*4+3],
                   brow + ((u ^ (uint32_t)(rk & 7)) * 16));
            LDSM4T(bl[q*4+0], bl[q*4+1], bl[q*4+2], bl[q*4+3],
                   brow + (((u | 4) ^ (uint32_t)(rk & 7)) * 16));
        }
#pragma unroll
        for (int mt = 0; mt < 2; mt++) {
            int rA = wid * 32 + mt * 16 + (lid & 15);
            uint32_t arow = abuf + (uint32_t)rA * 80;
            uint32_t ah0, ah1, ah2, ah3, al0, al1, al2, al3;
            LDSM4(ah0, ah1, ah2, ah3, arow + (uint32_t)half * 16);        // hi units 0,1
            LDSM4(al0, al1, al2, al3, arow + (uint32_t)(half + 2) * 16);  // lo units 2,3
#pragma unroll
            for (int nt = 0; nt < 4; nt++) {
                MMA16816(acc[mt][nt], ah0, ah1, ah2, ah3, bh[nt*2], bh[nt*2+1]);
                MMA16816(acc[mt][nt], ah0, ah1, ah2, ah3, bl[nt*2], bl[nt*2+1]);
                MMA16816(acc[mt][nt], al0, al1, al2, al3, bh[nt*2], bh[nt*2+1]);
            }
        }
    };

    // ---- prologue: stages 0,1 in flight; pool(0) ----
    issue(0); CP_COMMIT();
    issue(1); CP_COMMIT();
    CP_WAIT1();                 // chunk 0 landed (this thread)
    __syncthreads();            // visible to all
    pool(0);
    __syncthreads();

    // ---- main loop: one barrier per chunk ----
    for (int i = 0; i < NCHK; i++) {
        if (i + 2 < NCHK) issue(i + 2);
        CP_COMMIT();            // always commit (empty ok) to keep group math exact
        mma(i);
        if (i + 1 < NCHK) {
            CP_WAIT1();         // chunk i+1 landed
            pool(i + 1);
            __syncthreads();    // B(i+1) + A(i+1) visible; all warps done mma(i)
        }
    }

    // ---- epilogue ----
#pragma unroll
    for (int mt = 0; mt < 2; mt++) {
#pragma unroll
        for (int nt = 0; nt < 4; nt++) {
            int m = wid * 32 + mt * 16 + (lid >> 2);
            int n = n0 + nt * 8 + ((lid & 3) << 1);
            int b2 = n / NPB, p2 = n - b2 * NPB;
            float* o = out + ((size_t)b2 * COUT + m) * NPB + p2;
            *(float2*)o = make_float2(acc[mt][nt][0], acc[mt][nt][1]);
            *(float2*)(o + 8 * NPB) = make_float2(acc[mt][nt][2], acc[mt][nt][3]);
        }
    }
}

// ============================================================================
extern "C" void kernel_launch(void* const* d_in, const int* in_sizes, int n_in,
                              void* d_out, int out_size) {
    const float* x  = (const float*)d_in[0];
    const float* gw = (const float*)d_in[1];
    const float* gb = (const float*)d_in[2];
    const float* gm = (const float*)d_in[3];
    const float* gv = (const float*)d_in[4];
    const float* cw = (const float*)d_in[5];
    float* out = (float*)d_out;

    cudaFuncSetAttribute(fused_all, cudaFuncAttributeMaxDynamicSharedMemorySize, SMEM_TOT);
    prep_w<<<(COUT * CIN) / 512, 512>>>(cw);
    fused_all<<<NTOT / BN, 256, SMEM_TOT>>>(x, gw, gb, gm, gv, out);
}

// round 7
// speedup vs baseline: 1.3027x; 1.3027x over previous
#include <cuda_runtime.h>
#include <cuda_bf16.h>
#include <cstdint>

// ---------------- problem constants ----------------
#define B_    16
#define CIN   512
#define COUT  256
#define H_    56
#define W_    56
#define HO    28
#define WO    28
#define NPB   784
#define NTOT  (B_ * NPB)          // 12544
#define KSTK  1024                // [0,512)=hi, [512,1024)=lo

// scratch
__device__ __align__(16) __nv_bfloat16 g_ys[(size_t)NTOT * KSTK];   // Y^T [n][k]
__device__ __align__(16) __nv_bfloat16 g_wf[16 * COUT * 64];        // [j][m][hi32|lo32]

__device__ __forceinline__ uint32_t smem_u32(const void* p) {
    uint32_t a;
    asm("{ .reg .u64 t; cvta.to.shared.u64 t, %1; cvt.u32.u64 %0, t; }" : "=r"(a) : "l"(p));
    return a;
}
#define CP_ASYNC16(dst_u32, src_ptr) \
    asm volatile("cp.async.cg.shared.global [%0], [%1], 16;" :: "r"(dst_u32), "l"(src_ptr))
#define CP_COMMIT() asm volatile("cp.async.commit_group;")
#define CP_WAIT2()  asm volatile("cp.async.wait_group 2;")

#define LDSM4(R0, R1, R2, R3, A) \
    asm volatile("ldmatrix.sync.aligned.m8n8.x4.shared.b16 {%0,%1,%2,%3}, [%4];" \
                 : "=r"(R0), "=r"(R1), "=r"(R2), "=r"(R3) : "r"(A))
#define MMA16816(C, A0, A1, A2, A3, B0, B1) \
    asm volatile("mma.sync.aligned.m16n8k16.row.col.f32.bf16.bf16.f32 " \
                 "{%0,%1,%2,%3}, {%4,%5,%6,%7}, {%8,%9}, {%0,%1,%2,%3};" \
                 : "+f"((C)[0]), "+f"((C)[1]), "+f"((C)[2]), "+f"((C)[3]) \
                 : "r"(A0), "r"(A1), "r"(A2), "r"(A3), "r"(B0), "r"(B1))

// ============================================================================
// Kernel 1: BN+ReLU+pool+split+transpose (rows y<8) ; W split (row y==8)
// ============================================================================
__global__ __launch_bounds__(256) void fuse_pool(const float* __restrict__ x,
                                                 const float* __restrict__ gamma,
                                                 const float* __restrict__ beta,
                                                 const float* __restrict__ mean,
                                                 const float* __restrict__ var,
                                                 const float* __restrict__ w) {
    const int tid = threadIdx.x;

    if (blockIdx.y == 8) {                   // ---- W prep: 128 blocks ----
        if (blockIdx.x < 128) {
            int base = (blockIdx.x * 256 + tid) * 4;
            float4 v = *(const float4*)(w + base);
            int m = base >> 9, k = base & 511;
            __nv_bfloat16* d = g_wf + (size_t)(k >> 5) * (COUT * 64) + m * 64 + (k & 31);
            float vv[4] = {v.x, v.y, v.z, v.w};
#pragma unroll
            for (int e = 0; e < 4; e++) {
                __nv_bfloat16 hi = __float2bfloat16(vv[e]);
                d[e]      = hi;
                d[e + 32] = __float2bfloat16(vv[e] - __bfloat162float(hi));
            }
        }
        return;
    }

    __shared__ __nv_bfloat16 shi[64][66];
    __shared__ __nv_bfloat16 slo[64][66];
    __shared__ float ssc[64], ssh[64];

    const int n0 = blockIdx.x * 64;
    const int c0 = blockIdx.y * 64;

    if (tid < 64) {
        int c = c0 + tid;
        float sc = gamma[c] * rsqrtf(var[c] + 1e-5f);
        ssc[tid] = sc;
        ssh[tid] = beta[c] - mean[c] * sc;
    }
    __syncthreads();

    const int nl = tid & 63;
    const int n  = n0 + nl;
    const int b  = n / NPB;
    const int p  = n % NPB;
    const int ho = p / WO, wo = p % WO;
    const float* xb = x + (((long)b * CIN) * H_ + 2 * ho) * W_ + 2 * wo;
    const int cb = tid >> 6;

#pragma unroll
    for (int ci = 0; ci < 16; ci++) {
        int cl = cb * 16 + ci;
        const float* xp = xb + (long)(c0 + cl) * (H_ * W_);
        float2 r0 = *(const float2*)xp;
        float2 r1 = *(const float2*)(xp + W_);
        float sc = ssc[cl], sh = ssh[cl];
        float v = fmaxf(fmaf(r0.x, sc, sh), 0.f) + fmaxf(fmaf(r0.y, sc, sh), 0.f)
                + fmaxf(fmaf(r1.x, sc, sh), 0.f) + fmaxf(fmaf(r1.y, sc, sh), 0.f);
        v *= 0.25f;
        __nv_bfloat16 hi = __float2bfloat16(v);
        shi[cl][nl] = hi;
        slo[cl][nl] = __float2bfloat16(v - __bfloat162float(hi));
    }
    __syncthreads();

    const int kl = tid & 63;
    const int nb = tid >> 6;
#pragma unroll
    for (int ni = 0; ni < 16; ni++) {
        int nl2 = nb * 16 + ni;
        size_t base = (size_t)(n0 + nl2) * KSTK + c0 + kl;
        g_ys[base]       = shi[kl][nl2];
        g_ys[base + 512] = slo[kl][nl2];
    }
}

// ============================================================================
// Kernel 2: bf16x3 GEMM, BM=128 BN=64 BK=32, 4-stage cp.async, 2 CTAs/SM.
// A rows (m): 144B pitch = hi k0..31 (units 0-3) | lo (units 4-7) | 16B pad.
// B rows (n): 144B pitch = same unit layout. gcd(9,8)=1 -> conflict-free.
// ============================================================================
#define BM    128
#define BN    64
#define NCH   16
#define STG   4
#define PITCH 144
#define A_BYTES (BM * PITCH)       // 18432
#define B_BYTES (BN * PITCH)       // 9216
#define STAGE_B (A_BYTES + B_BYTES)  // 27648
#define SMEM_TOT (STG * STAGE_B)     // 110592

__global__ __launch_bounds__(256, 2) void gemm_mma(float* __restrict__ out) {
    extern __shared__ char smem[];
    const uint32_t sb = smem_u32(smem);
    const int tid = threadIdx.x;
    const int lid = tid & 31, wid = tid >> 5;
    const int n0 = blockIdx.x * BN;
    const int m0 = blockIdx.y * BM;

    // ---- producer mappings ----
    const int am  = tid & 127;          // A row
    const int asg = tid >> 7;           // A segment (0:hi, 1:lo) -> units 4*asg..
    const __nv_bfloat16* awsrc = g_wf + (size_t)(m0 + am) * 64 + asg * 32;
    const uint32_t adst0 = sb + (uint32_t)am * PITCH + asg * 64;

    const int bn  = tid & 63;           // B row
    const int bsg = tid >> 6;           // 0,1: hi units 2s..2s+1 ; 2,3: lo
    const __nv_bfloat16* bsrc0 = g_ys + (size_t)(n0 + bn) * KSTK
                               + (bsg < 2 ? bsg * 16 : 512 + (bsg - 2) * 16);
    const uint32_t bdst0 = sb + A_BYTES + (uint32_t)bn * PITCH + bsg * 32;

    auto load_stage = [&](int j) {
        const uint32_t s = (uint32_t)(j & (STG - 1)) * STAGE_B;
        const __nv_bfloat16* aw = awsrc + (size_t)j * (COUT * 64);
        CP_ASYNC16(adst0 + s,      aw);
        CP_ASYNC16(adst0 + s + 16, aw + 8);
        CP_ASYNC16(adst0 + s + 32, aw + 16);
        CP_ASYNC16(adst0 + s + 48, aw + 24);
        const __nv_bfloat16* bw = bsrc0 + j * 32;
        CP_ASYNC16(bdst0 + s,      bw);
        CP_ASYNC16(bdst0 + s + 16, bw + 8);
    };

    // ---- consumer mapping: 8 warps, tile 32m x 32n ----
    const int wm = wid & 3, wn = wid >> 2;
    const int half  = lid >> 4;
    const int bhalf = (lid >> 3) & 1;
    const int brow0 = wn * 32 + (lid & 7) + ((lid >> 4) << 3);
    const int brow1 = brow0 + 16;

    float acc[2][4][4];
#pragma unroll
    for (int a = 0; a < 2; a++)
#pragma unroll
        for (int b = 0; b < 4; b++)
#pragma unroll
            for (int c = 0; c < 4; c++) acc[a][b][c] = 0.f;

    // ---- prologue ----
#pragma unroll
    for (int j = 0; j < STG - 1; j++) { load_stage(j); CP_COMMIT(); }

    for (int i = 0; i < NCH; i++) {
        CP_WAIT2();
        __syncthreads();
        if (i + STG - 1 < NCH) load_stage(i + STG - 1);
        CP_COMMIT();

        const uint32_t sA = sb + (uint32_t)(i & (STG - 1)) * STAGE_B;
        const uint32_t sB = sA + A_BYTES;
#pragma unroll
        for (int ks = 0; ks < 2; ks++) {
            const uint32_t ub = (uint32_t)(2 * ks + bhalf);
            uint32_t bh[8], bl[8];
            LDSM4(bh[0], bh[1], bh[2], bh[3], sB + (uint32_t)brow0 * PITCH + ub * 16);
            LDSM4(bh[4], bh[5], bh[6], bh[7], sB + (uint32_t)brow1 * PITCH + ub * 16);
            LDSM4(bl[0], bl[1], bl[2], bl[3], sB + (uint32_t)brow0 * PITCH + (ub + 4) * 16);
            LDSM4(bl[4], bl[5], bl[6], bl[7], sB + (uint32_t)brow1 * PITCH + (ub + 4) * 16);
            const uint32_t uah = (uint32_t)(2 * ks + half);
#pragma unroll
            for (int mt = 0; mt < 2; mt++) {
                uint32_t arow = sA + (uint32_t)(wm * 32 + mt * 16 + (lid & 15)) * PITCH;
                uint32_t ah0, ah1, ah2, ah3, al0, al1, al2, al3;
                LDSM4(ah0, ah1, ah2, ah3, arow + uah * 16);
                LDSM4(al0, al1, al2, al3, arow + (uah + 4) * 16);
#pragma unroll
                for (int nt = 0; nt < 4; nt++) {
                    MMA16816(acc[mt][nt], ah0, ah1, ah2, ah3, bh[nt*2], bh[nt*2+1]);
                    MMA16816(acc[mt][nt], ah0, ah1, ah2, ah3, bl[nt*2], bl[nt*2+1]);
                    MMA16816(acc[mt][nt], al0, al1, al2, al3, bh[nt*2], bh[nt*2+1]);
                }
            }
        }
    }

    // ---- epilogue: direct float2 stores ----
#pragma unroll
    for (int mt = 0; mt < 2; mt++) {
#pragma unroll
        for (int nt = 0; nt < 4; nt++) {
            int m = m0 + wm * 32 + mt * 16 + (lid >> 2);
            int n = n0 + wn * 32 + nt * 8 + ((lid & 3) << 1);
            int b2 = n / NPB, p2 = n - b2 * NPB;
            float* o = out + ((size_t)b2 * COUT + m) * NPB + p2;
            *(float2*)o = make_float2(acc[mt][nt][0], acc[mt][nt][1]);
            *(float2*)(o + 8 * NPB) = make_float2(acc[mt][nt][2], acc[mt][nt][3]);
        }
    }
}

// ============================================================================
extern "C" void kernel_launch(void* const* d_in, const int* in_sizes, int n_in,
                              void* d_out, int out_size) {
    const float* x  = (const float*)d_in[0];
    const float* gw = (const float*)d_in[1];
    const float* gb = (const float*)d_in[2];
    const float* gm = (const float*)d_in[3];
    const float* gv = (const float*)d_in[4];
    const float* cw = (const float*)d_in[5];
    float* out = (float*)d_out;

    cudaFuncSetAttribute(gemm_mma, cudaFuncAttributeMaxDynamicSharedMemorySize, SMEM_TOT);

    fuse_pool<<<dim3(NTOT / 64, 9), 256>>>(x, gw, gb, gm, gv, cw);
    gemm_mma<<<dim3(NTOT / BN, COUT / BM), 256, SMEM_TOT>>>(out);
}

// round 8
// speedup vs baseline: 1.9879x; 1.5260x over previous
#include <cuda_runtime.h>
#include <cuda_fp16.h>
#include <cstdint>

// ---------------- problem constants ----------------
#define B_    16
#define CIN   512
#define COUT  256
#define H_    56
#define W_    56
#define HO    28
#define WO    28
#define NPB   784
#define NTOT  (B_ * NPB)          // 12544

// scratch: fp16 single-precision-split-free operands
__device__ __align__(16) __half g_yh[(size_t)NTOT * CIN];   // Y^T [n][k]  (12.8 MB)
__device__ __align__(16) __half g_wh[8 * COUT * 64];        // [j][m][k64] (256 KB)

__device__ __forceinline__ uint32_t smem_u32(const void* p) {
    uint32_t a;
    asm("{ .reg .u64 t; cvta.to.shared.u64 t, %1; cvt.u32.u64 %0, t; }" : "=r"(a) : "l"(p));
    return a;
}
#define CP_ASYNC16(dst_u32, src_ptr) \
    asm volatile("cp.async.cg.shared.global [%0], [%1], 16;" :: "r"(dst_u32), "l"(src_ptr))
#define CP_COMMIT() asm volatile("cp.async.commit_group;")
#define CP_WAIT2()  asm volatile("cp.async.wait_group 2;")

#define LDSM4(R0, R1, R2, R3, A) \
    asm volatile("ldmatrix.sync.aligned.m8n8.x4.shared.b16 {%0,%1,%2,%3}, [%4];" \
                 : "=r"(R0), "=r"(R1), "=r"(R2), "=r"(R3) : "r"(A))
#define MMAF16(C, A0, A1, A2, A3, B0, B1) \
    asm volatile("mma.sync.aligned.m16n8k16.row.col.f32.f16.f16.f32 " \
                 "{%0,%1,%2,%3}, {%4,%5,%6,%7}, {%8,%9}, {%0,%1,%2,%3};" \
                 : "+f"((C)[0]), "+f"((C)[1]), "+f"((C)[2]), "+f"((C)[3]) \
                 : "r"(A0), "r"(A1), "r"(A2), "r"(A3), "r"(B0), "r"(B1))

// ============================================================================
// Kernel 1: BN+ReLU+pool+fp16+transpose (rows y<8); W fp32->fp16 (row y==8)
// ============================================================================
__global__ __launch_bounds__(256) void fuse_pool(const float* __restrict__ x,
                                                 const float* __restrict__ gamma,
                                                 const float* __restrict__ beta,
                                                 const float* __restrict__ mean,
                                                 const float* __restrict__ var,
                                                 const float* __restrict__ w) {
    const int tid = threadIdx.x;

    if (blockIdx.y == 8) {                   // ---- W prep: 128 blocks ----
        if (blockIdx.x < 128) {
            int base = (blockIdx.x * 256 + tid) * 4;
            float4 v = *(const float4*)(w + base);
            int m = base >> 9, k = base & 511;
            __half* d = g_wh + (size_t)(k >> 6) * (COUT * 64) + m * 64 + (k & 63);
            d[0] = __float2half(v.x);
            d[1] = __float2half(v.y);
            d[2] = __float2half(v.z);
            d[3] = __float2half(v.w);
        }
        return;
    }

    __shared__ __half sy[64][66];
    __shared__ float ssc[64], ssh[64];

    const int n0 = blockIdx.x * 64;
    const int c0 = blockIdx.y * 64;

    if (tid < 64) {
        int c = c0 + tid;
        float sc = gamma[c] * rsqrtf(var[c] + 1e-5f);
        ssc[tid] = sc;
        ssh[tid] = beta[c] - mean[c] * sc;
    }
    __syncthreads();

    const int nl = tid & 63;
    const int n  = n0 + nl;
    const int b  = n / NPB;
    const int p  = n % NPB;
    const int ho = p / WO, wo = p % WO;
    const float* xb = x + (((long)b * CIN) * H_ + 2 * ho) * W_ + 2 * wo;
    const int cb = tid >> 6;

#pragma unroll
    for (int ci = 0; ci < 16; ci++) {
        int cl = cb * 16 + ci;
        const float* xp = xb + (long)(c0 + cl) * (H_ * W_);
        float2 r0 = *(const float2*)xp;
        float2 r1 = *(const float2*)(xp + W_);
        float sc = ssc[cl], sh = ssh[cl];
        float v = fmaxf(fmaf(r0.x, sc, sh), 0.f) + fmaxf(fmaf(r0.y, sc, sh), 0.f)
                + fmaxf(fmaf(r1.x, sc, sh), 0.f) + fmaxf(fmaf(r1.y, sc, sh), 0.f);
        sy[cl][nl] = __float2half(v * 0.25f);
    }
    __syncthreads();

    const int kl = tid & 63;
    const int nb = tid >> 6;
#pragma unroll
    for (int ni = 0; ni < 16; ni++) {
        int nl2 = nb * 16 + ni;
        g_yh[(size_t)(n0 + nl2) * CIN + c0 + kl] = sy[kl][nl2];
    }
}

// ============================================================================
// Kernel 2: fp16 GEMM  C[256,12544] = W * Y^T, fp32 accum.
// BM=128 BN=64 BK=64, 8 chunks, 4-stage cp.async, 2 CTAs/SM.
// Rows: 144B pitch = 8 x 16B data units (k0..63) + 16B pad; gcd(9,8)=1
// -> cp.async stores and LDSM reads both bank-conflict-free, no XOR.
// ============================================================================
#define BM    128
#define BN    64
#define NCH   8
#define STG   4
#define PITCH 144
#define A_BYTES (BM * PITCH)         // 18432
#define B_BYTES (BN * PITCH)         // 9216
#define STAGE_B (A_BYTES + B_BYTES)  // 27648
#define SMEM_TOT (STG * STAGE_B)     // 110592

__global__ __launch_bounds__(256, 2) void gemm_mma(float* __restrict__ out) {
    extern __shared__ char smem[];
    const uint32_t sb = smem_u32(smem);
    const int tid = threadIdx.x;
    const int lid = tid & 31, wid = tid >> 5;
    const int n0 = blockIdx.x * BN;
    const int m0 = blockIdx.y * BM;

    // ---- producer mappings ----
    const int am = tid & 127;           // A row (m)
    const int ah = tid >> 7;            // 0/1 -> units 4ah..4ah+3
    const __half* asrc = g_wh + (size_t)(m0 + am) * 64 + ah * 32;
    const uint32_t adst = sb + (uint32_t)am * PITCH + ah * 64;

    const int bn = tid & 63;            // B row (n)
    const int bs = tid >> 6;            // 0..3 -> units 2bs, 2bs+1
    const __half* bsrc = g_yh + (size_t)(n0 + bn) * CIN + bs * 16;
    const uint32_t bdst = sb + A_BYTES + (uint32_t)bn * PITCH + bs * 32;

    auto load_stage = [&](int j) {
        const uint32_t s = (uint32_t)(j & (STG - 1)) * STAGE_B;
        const __half* aw = asrc + (size_t)j * (COUT * 64);
        CP_ASYNC16(adst + s,      aw);
        CP_ASYNC16(adst + s + 16, aw + 8);
        CP_ASYNC16(adst + s + 32, aw + 16);
        CP_ASYNC16(adst + s + 48, aw + 24);
        const __half* bw = bsrc + (size_t)j * 64;
        CP_ASYNC16(bdst + s,      bw);
        CP_ASYNC16(bdst + s + 16, bw + 8);
    };

    // ---- consumer mapping: 8 warps, tile 32m x 32n ----
    const int wm = wid & 3, wn = wid >> 2;
    const int half  = lid >> 4;
    const int bhalf = (lid >> 3) & 1;
    const int brow0 = wn * 32 + (lid & 7) + ((lid >> 4) << 3);
    const int brow1 = brow0 + 16;

    float acc[2][4][4];
#pragma unroll
    for (int a = 0; a < 2; a++)
#pragma unroll
        for (int b = 0; b < 4; b++)
#pragma unroll
            for (int c = 0; c < 4; c++) acc[a][b][c] = 0.f;

    // ---- prologue ----
#pragma unroll
    for (int j = 0; j < STG - 1; j++) { load_stage(j); CP_COMMIT(); }

    for (int i = 0; i < NCH; i++) {
        CP_WAIT2();
        __syncthreads();
        if (i + STG - 1 < NCH) load_stage(i + STG - 1);
        CP_COMMIT();

        const uint32_t sA = sb + (uint32_t)(i & (STG - 1)) * STAGE_B;
        const uint32_t sB = sA + A_BYTES;
#pragma unroll
        for (int ks = 0; ks < 4; ks++) {
            const uint32_t ub = (uint32_t)(2 * ks + bhalf);
            uint32_t b0, b1, b2, b3, b4, b5, b6, b7;
            LDSM4(b0, b1, b2, b3, sB + (uint32_t)brow0 * PITCH + ub * 16);
            LDSM4(b4, b5, b6, b7, sB + (uint32_t)brow1 * PITCH + ub * 16);
            const uint32_t ua = (uint32_t)(2 * ks + half);
#pragma unroll
            for (int mt = 0; mt < 2; mt++) {
                uint32_t arow = sA + (uint32_t)(wm * 32 + mt * 16 + (lid & 15)) * PITCH;
                uint32_t a0, a1, a2, a3;
                LDSM4(a0, a1, a2, a3, arow + ua * 16);
                MMAF16(acc[mt][0], a0, a1, a2, a3, b0, b1);
                MMAF16(acc[mt][1], a0, a1, a2, a3, b2, b3);
                MMAF16(acc[mt][2], a0, a1, a2, a3, b4, b5);
                MMAF16(acc[mt][3], a0, a1, a2, a3, b6, b7);
            }
        }
    }

    // ---- epilogue: direct float2 stores ----
#pragma unroll
    for (int mt = 0; mt < 2; mt++) {
#pragma unroll
        for (int nt = 0; nt < 4; nt++) {
            int m = m0 + wm * 32 + mt * 16 + (lid >> 2);
            int n = n0 + wn * 32 + nt * 8 + ((lid & 3) << 1);
            int b2 = n / NPB, p2 = n - b2 * NPB;
            float* o = out + ((size_t)b2 * COUT + m) * NPB + p2;
            *(float2*)o = make_float2(acc[mt][nt][0], acc[mt][nt][1]);
            *(float2*)(o + 8 * NPB) = make_float2(acc[mt][nt][2], acc[mt][nt][3]);
        }
    }
}

// ============================================================================
extern "C" void kernel_launch(void* const* d_in, const int* in_sizes, int n_in,
                              void* d_out, int out_size) {
    const float* x  = (const float*)d_in[0];
    const float* gw = (const float*)d_in[1];
    const float* gb = (const float*)d_in[2];
    const float* gm = (const float*)d_in[3];
    const float* gv = (const float*)d_in[4];
    const float* cw = (const float*)d_in[5];
    float* out = (float*)d_out;

    cudaFuncSetAttribute(gemm_mma, cudaFuncAttributeMaxDynamicSharedMemorySize, SMEM_TOT);

    fuse_pool<<<dim3(NTOT / 64, 9), 256>>>(x, gw, gb, gm, gv, cw);
    gemm_mma<<<dim3(NTOT / BN, COUT / BM), 256, SMEM_TOT>>>(out);
}

// round 9
// speedup vs baseline: 2.9443x; 1.4812x over previous
#include <cuda_runtime.h>
#include <cuda_fp16.h>
#include <cstdint>

// ---------------- problem constants ----------------
#define B_    16
#define CIN   512
#define COUT  256
#define H_    56
#define W_    56
#define HO    28
#define WO    28
#define NPB   784
#define NTOT  (B_ * NPB)          // 12544
#define HW    (H_ * W_)
#define NBLK  (NTOT / 64)         // 196 n-blocks

// scratch, pre-swizzled block layouts (written by fuse_pool, TMA-bulk read by gemm)
// g_wh: [chunk j (8)][mblk (2)][128 rows x 128B, XOR-swizzled]   = 256 KB
// g_yh: [chunk j (8)][nblk (196)][64 rows x 128B, XOR-swizzled]  = 12.8 MB
__device__ __align__(1024) __half g_wh[8 * 2 * 128 * 64];
__device__ __align__(1024) __half g_yh[(size_t)8 * NBLK * 64 * 64];

__device__ __forceinline__ uint32_t smem_u32(const void* p) {
    uint32_t a;
    asm("{ .reg .u64 t; cvta.to.shared.u64 t, %1; cvt.u32.u64 %0, t; }" : "=r"(a) : "l"(p));
    return a;
}
#define MBAR_INIT(a, c) \
    asm volatile("mbarrier.init.shared.b64 [%0], %1;" :: "r"(a), "r"(c) : "memory")
#define MBAR_EXPECT_TX(a, b) \
    asm volatile("mbarrier.arrive.expect_tx.shared.b64 _, [%0], %1;" :: "r"(a), "r"(b) : "memory")
__device__ __forceinline__ void mbar_wait(uint32_t a, uint32_t parity) {
    asm volatile(
        "{\n\t.reg .pred P;\n\t"
        "W_%=:\n\t"
        "mbarrier.try_wait.parity.acquire.cta.shared::cta.b64 P, [%0], %1, 0x989680;\n\t"
        "@P bra.uni D_%=;\n\t"
        "bra.uni W_%=;\n\t"
        "D_%=:\n\t}"
        :: "r"(a), "r"(parity) : "memory");
}
#define BULK_G2S(dst, src, bytes, mbar) \
    asm volatile("cp.async.bulk.shared::cluster.global.mbarrier::complete_tx::bytes " \
                 "[%0], [%1], %2, [%3];" \
                 :: "r"(dst), "l"(src), "r"(bytes), "r"(mbar) : "memory")

#define LDSM4(R0, R1, R2, R3, A) \
    asm volatile("ldmatrix.sync.aligned.m8n8.x4.shared.b16 {%0,%1,%2,%3}, [%4];" \
                 : "=r"(R0), "=r"(R1), "=r"(R2), "=r"(R3) : "r"(A))
#define MMAF16(C, A0, A1, A2, A3, B0, B1) \
    asm volatile("mma.sync.aligned.m16n8k16.row.col.f32.f16.f16.f32 " \
                 "{%0,%1,%2,%3}, {%4,%5,%6,%7}, {%8,%9}, {%0,%1,%2,%3};" \
                 : "+f"((C)[0]), "+f"((C)[1]), "+f"((C)[2]), "+f"((C)[3]) \
                 : "r"(A0), "r"(A1), "r"(A2), "r"(A3), "r"(B0), "r"(B1))

// ============================================================================
// Kernel 1: BN+ReLU+pool -> fp16, swizzled n-block tiles (rows y<8)
//           W fp32 -> fp16, swizzled m-block tiles (row y==8)
// ============================================================================
__global__ __launch_bounds__(256) void fuse_pool(const float* __restrict__ x,
                                                 const float* __restrict__ gamma,
                                                 const float* __restrict__ beta,
                                                 const float* __restrict__ mean,
                                                 const float* __restrict__ var,
                                                 const float* __restrict__ w) {
    const int tid = threadIdx.x;

    if (blockIdx.y == 8) {                   // ---- W prep (128 blocks used) ----
        if (blockIdx.x < 128) {
            int base = (blockIdx.x * 256 + tid) * 4;        // element index
            float4 v = *(const float4*)(w + base);
            int m = base >> 9;               // 0..255
            int k = base & 511;
            int mr = m & 127;
            uint32_t u   = (uint32_t)((k & 63) >> 3);
            uint32_t sub = (uint32_t)(k & 7) * 2;            // 0 or 8
            __half h[4] = {__float2half(v.x), __float2half(v.y),
                           __float2half(v.z), __float2half(v.w)};
            char* d = (char*)g_wh + ((size_t)(k >> 6) * 2 + (m >> 7)) * 16384
                    + (uint32_t)mr * 128 + ((u ^ (uint32_t)(mr & 7)) * 16) + sub;
            *(uint2*)d = *(uint2*)h;
        }
        return;
    }

    __shared__ __half sy[64][66];
    __shared__ float ssc[64], ssh[64];

    const int n0 = blockIdx.x * 64;
    const int c0 = blockIdx.y * 64;

    if (tid < 64) {
        int c = c0 + tid;
        float sc = gamma[c] * rsqrtf(var[c] + 1e-5f);
        ssc[tid] = sc;
        ssh[tid] = beta[c] - mean[c] * sc;
    }
    __syncthreads();

    // phase A: each thread pools 2 adjacent outputs via float4 loads
    const int pr2 = tid & 31;            // outputs n0+2pr2, n0+2pr2+1
    const int cb  = tid >> 5;            // 0..7
    const int n  = n0 + 2 * pr2;
    const int b  = n / NPB;
    const int p  = n - b * NPB;
    const int ho = p / WO, wo = p - ho * WO;      // wo even; pair same row
    const float* xb = x + ((size_t)b * CIN * H_ + 2 * ho) * W_ + 2 * wo;

#pragma unroll
    for (int ci = 0; ci < 8; ci++) {
        int cl = ci * 8 + cb;
        const float* xp = xb + (size_t)(c0 + cl) * HW;
        float4 r0 = *(const float4*)xp;
        float4 r1 = *(const float4*)(xp + W_);
        float sc = ssc[cl], sh = ssh[cl];
        float v0 = fmaxf(fmaf(r0.x, sc, sh), 0.f) + fmaxf(fmaf(r0.y, sc, sh), 0.f)
                 + fmaxf(fmaf(r1.x, sc, sh), 0.f) + fmaxf(fmaf(r1.y, sc, sh), 0.f);
        float v1 = fmaxf(fmaf(r0.z, sc, sh), 0.f) + fmaxf(fmaf(r0.w, sc, sh), 0.f)
                 + fmaxf(fmaf(r1.z, sc, sh), 0.f) + fmaxf(fmaf(r1.w, sc, sh), 0.f);
        sy[cl][2 * pr2]     = __float2half(v0 * 0.25f);
        sy[cl][2 * pr2 + 1] = __float2half(v1 * 0.25f);
    }
    __syncthreads();

    // phase B: write swizzled tile (chunk = c0/64, nblk = n0/64), coalesced rows
    const int kl = tid & 63;
    const int nb = tid >> 6;
    const uint32_t u   = (uint32_t)(kl >> 3);
    const uint32_t sub = (uint32_t)(kl & 7) * 2;
    char* base = (char*)g_yh + ((size_t)(c0 >> 6) * NBLK + (n0 >> 6)) * 8192;
#pragma unroll
    for (int ni = 0; ni < 16; ni++) {
        int nl2 = nb * 16 + ni;
        *(__half*)(base + (uint32_t)nl2 * 128
                   + ((u ^ (uint32_t)(nl2 & 7)) * 16) + sub) = sy[kl][nl2];
    }
}

// ============================================================================
// Kernel 2: fp16 GEMM via TMA bulk loads. BM=128 BN=64 BK=64, 8 chunks,
// 4-stage mbarrier ring, 2 CTAs/SM. Stage = A 16KB + B 8KB, one bulk each.
// ============================================================================
#define NCH     8
#define STG     4
#define A_BYTES 16384
#define B_BYTES 8192
#define STAGE_B 24576
#define MBAR_OFF (STG * STAGE_B)         // 98304
#define SMEM_TOT (MBAR_OFF + 64)

__global__ __launch_bounds__(256, 2) void gemm_mma(float* __restrict__ out) {
    extern __shared__ char smem[];
    const uint32_t sb = smem_u32(smem);
    const int tid = threadIdx.x;
    const int lid = tid & 31, wid = tid >> 5;
    const int nblk = blockIdx.x;             // n0 = nblk*64
    const int mblk = blockIdx.y;             // m0 = mblk*128
    const int n0 = nblk * 64;
    const int m0 = mblk * 128;

    if (tid == 0) {
#pragma unroll
        for (int s = 0; s < STG; s++) MBAR_INIT(sb + MBAR_OFF + s * 8, 1);
    }
    __syncthreads();

    auto issue = [&](int j) {
        const int slot = j & (STG - 1);
        const uint32_t s = sb + (uint32_t)slot * STAGE_B;
        const uint32_t mb = sb + MBAR_OFF + slot * 8;
        MBAR_EXPECT_TX(mb, STAGE_B);
        const char* aSrc = (const char*)g_wh + ((size_t)j * 2 + mblk) * A_BYTES;
        const char* bSrc = (const char*)g_yh + ((size_t)j * NBLK + nblk) * B_BYTES;
        BULK_G2S(s, aSrc, A_BYTES, mb);
        BULK_G2S(s + A_BYTES, bSrc, B_BYTES, mb);
    };

    if (tid == 0) { issue(0); issue(1); issue(2); }

    // consumer mapping: 8 warps, tile 32m x 32n
    const int wm = wid & 3, wn = wid >> 2;
    const int half  = lid >> 4;
    const int bhalf = (lid >> 3) & 1;
    const int brow0 = wn * 32 + (lid & 7) + ((lid >> 4) << 3);
    const int brow1 = brow0 + 16;
    const int arow0 = wm * 32 + (lid & 15);

    float acc[2][4][4];
#pragma unroll
    for (int a = 0; a < 2; a++)
#pragma unroll
        for (int b = 0; b < 4; b++)
#pragma unroll
            for (int c = 0; c < 4; c++) acc[a][b][c] = 0.f;

    for (int i = 0; i < NCH; i++) {
        __syncthreads();                       // slot (i+3)&3 readers done
        if (tid == 0 && i + STG - 1 < NCH) issue(i + STG - 1);
        mbar_wait(sb + MBAR_OFF + (i & (STG - 1)) * 8, (uint32_t)((i >> 2) & 1));

        const uint32_t sA = sb + (uint32_t)(i & (STG - 1)) * STAGE_B;
        const uint32_t sB = sA + A_BYTES;
#pragma unroll
        for (int ks = 0; ks < 4; ks++) {
            const uint32_t ub = (uint32_t)(2 * ks + bhalf);
            uint32_t b0, b1, b2, b3, b4, b5, b6, b7;
            LDSM4(b0, b1, b2, b3,
                  sB + (uint32_t)brow0 * 128 + ((ub ^ (uint32_t)(brow0 & 7)) * 16));
            LDSM4(b4, b5, b6, b7,
                  sB + (uint32_t)brow1 * 128 + ((ub ^ (uint32_t)(brow1 & 7)) * 16));
            const uint32_t ua = (uint32_t)(2 * ks + half);
#pragma unroll
            for (int mt = 0; mt < 2; mt++) {
                int rA = arow0 + mt * 16;
                uint32_t a0, a1, a2, a3;
                LDSM4(a0, a1, a2, a3,
                      sA + (uint32_t)rA * 128 + ((ua ^ (uint32_t)(rA & 7)) * 16));
                MMAF16(acc[mt][0], a0, a1, a2, a3, b0, b1);
                MMAF16(acc[mt][1], a0, a1, a2, a3, b2, b3);
                MMAF16(acc[mt][2], a0, a1, a2, a3, b4, b5);
                MMAF16(acc[mt][3], a0, a1, a2, a3, b6, b7);
            }
        }
    }

    // epilogue: direct float2 stores
#pragma unroll
    for (int mt = 0; mt < 2; mt++) {
#pragma unroll
        for (int nt = 0; nt < 4; nt++) {
            int m = m0 + wm * 32 + mt * 16 + (lid >> 2);
            int n = n0 + wn * 32 + nt * 8 + ((lid & 3) << 1);
            int b2 = n / NPB, p2 = n - b2 * NPB;
            float* o = out + ((size_t)b2 * COUT + m) * NPB + p2;
            *(float2*)o = make_float2(acc[mt][nt][0], acc[mt][nt][1]);
            *(float2*)(o + 8 * NPB) = make_float2(acc[mt][nt][2], acc[mt][nt][3]);
        }
    }
}

// ============================================================================
extern "C" void kernel_launch(void* const* d_in, const int* in_sizes, int n_in,
                              void* d_out, int out_size) {
    const float* x  = (const float*)d_in[0];
    const float* gw = (const float*)d_in[1];
    const float* gb = (const float*)d_in[2];
    const float* gm = (const float*)d_in[3];
    const float* gv = (const float*)d_in[4];
    const float* cw = (const float*)d_in[5];
    float* out = (float*)d_out;

    cudaFuncSetAttribute(gemm_mma, cudaFuncAttributeMaxDynamicSharedMemorySize, SMEM_TOT);

    fuse_pool<<<dim3(NBLK, 9), 256>>>(x, gw, gb, gm, gv, cw);
    gemm_mma<<<dim3(NBLK, 2), 256, SMEM_TOT>>>(out);
}

// round 10
// speedup vs baseline: 2.9570x; 1.0043x over previous
#include <cuda_runtime.h>
#include <cuda_fp16.h>
#include <cstdint>

// ---------------- problem constants ----------------
#define B_    16
#define CIN   512
#define COUT  256
#define H_    56
#define W_    56
#define HO    28
#define WO    28
#define NPB   784
#define NTOT  (B_ * NPB)          // 12544
#define HW    (H_ * W_)
#define NBLK  (NTOT / 64)         // 196 n-blocks

// scratch, pre-swizzled block layouts (written by fuse_pool, TMA-bulk read by gemm)
// g_wh: [chunk j (8)][mblk (2)][128 rows x 128B, XOR-swizzled]   = 256 KB
// g_yh: [chunk j (8)][nblk (196)][64 rows x 128B, XOR-swizzled]  = 12.8 MB
__device__ __align__(1024) __half g_wh[8 * 2 * 128 * 64];
__device__ __align__(1024) __half g_yh[(size_t)8 * NBLK * 64 * 64];

__device__ __forceinline__ uint32_t smem_u32(const void* p) {
    uint32_t a;
    asm("{ .reg .u64 t; cvta.to.shared.u64 t, %1; cvt.u32.u64 %0, t; }" : "=r"(a) : "l"(p));
    return a;
}
#define MBAR_INIT(a, c) \
    asm volatile("mbarrier.init.shared.b64 [%0], %1;" :: "r"(a), "r"(c) : "memory")
#define MBAR_EXPECT_TX(a, b) \
    asm volatile("mbarrier.arrive.expect_tx.shared.b64 _, [%0], %1;" :: "r"(a), "r"(b) : "memory")
__device__ __forceinline__ void mbar_wait(uint32_t a, uint32_t parity) {
    asm volatile(
        "{\n\t.reg .pred P;\n\t"
        "W_%=:\n\t"
        "mbarrier.try_wait.parity.acquire.cta.shared::cta.b64 P, [%0], %1, 0x989680;\n\t"
        "@P bra.uni D_%=;\n\t"
        "bra.uni W_%=;\n\t"
        "D_%=:\n\t}"
        :: "r"(a), "r"(parity) : "memory");
}
#define BULK_G2S(dst, src, bytes, mbar) \
    asm volatile("cp.async.bulk.shared::cluster.global.mbarrier::complete_tx::bytes " \
                 "[%0], [%1], %2, [%3];" \
                 :: "r"(dst), "l"(src), "r"(bytes), "r"(mbar) : "memory")

#define LDSM4(R0, R1, R2, R3, A) \
    asm volatile("ldmatrix.sync.aligned.m8n8.x4.shared.b16 {%0,%1,%2,%3}, [%4];" \
                 : "=r"(R0), "=r"(R1), "=r"(R2), "=r"(R3) : "r"(A))
#define MMAF16(C, A0, A1, A2, A3, B0, B1) \
    asm volatile("mma.sync.aligned.m16n8k16.row.col.f32.f16.f16.f32 " \
                 "{%0,%1,%2,%3}, {%4,%5,%6,%7}, {%8,%9}, {%0,%1,%2,%3};" \
                 : "+f"((C)[0]), "+f"((C)[1]), "+f"((C)[2]), "+f"((C)[3]) \
                 : "r"(A0), "r"(A1), "r"(A2), "r"(A3), "r"(B0), "r"(B1))

// ============================================================================
// Kernel 1: BN+ReLU+pool -> fp16, swizzled n-block tiles (rows y<8)
//           W fp32 -> fp16, swizzled m-block tiles (row y==8)
// ============================================================================
__global__ __launch_bounds__(256) void fuse_pool(const float* __restrict__ x,
                                                 const float* __restrict__ gamma,
                                                 const float* __restrict__ beta,
                                                 const float* __restrict__ mean,
                                                 const float* __restrict__ var,
                                                 const float* __restrict__ w) {
    const int tid = threadIdx.x;

    if (blockIdx.y == 8) {                   // ---- W prep (128 blocks used) ----
        if (blockIdx.x < 128) {
            int base = (blockIdx.x * 256 + tid) * 4;        // element index
            float4 v = *(const float4*)(w + base);
            int m = base >> 9;               // 0..255
            int k = base & 511;
            int mr = m & 127;
            uint32_t u   = (uint32_t)((k & 63) >> 3);
            uint32_t sub = (uint32_t)(k & 7) * 2;
            __half h[4] = {__float2half(v.x), __float2half(v.y),
                           __float2half(v.z), __float2half(v.w)};
            char* d = (char*)g_wh + ((size_t)(k >> 6) * 2 + (m >> 7)) * 16384
                    + (uint32_t)mr * 128 + ((u ^ (uint32_t)(mr & 7)) * 16) + sub;
            *(uint2*)d = *(uint2*)h;
        }
        return;
    }

    __shared__ __half sy[64][66];
    __shared__ float ssc[64], ssh[64];

    const int n0 = blockIdx.x * 64;
    const int c0 = blockIdx.y * 64;

    if (tid < 64) {
        int c = c0 + tid;
        float sc = gamma[c] * rsqrtf(var[c] + 1e-5f);
        ssc[tid] = sc;
        ssh[tid] = beta[c] - mean[c] * sc;
    }
    __syncthreads();

    // phase A: each thread pools 2 adjacent outputs via float4 loads
    const int pr2 = tid & 31;
    const int cb  = tid >> 5;
    const int n  = n0 + 2 * pr2;
    const int b  = n / NPB;
    const int p  = n - b * NPB;
    const int ho = p / WO, wo = p - ho * WO;
    const float* xb = x + ((size_t)b * CIN * H_ + 2 * ho) * W_ + 2 * wo;

#pragma unroll
    for (int ci = 0; ci < 8; ci++) {
        int cl = ci * 8 + cb;
        const float* xp = xb + (size_t)(c0 + cl) * HW;
        float4 r0 = *(const float4*)xp;
        float4 r1 = *(const float4*)(xp + W_);
        float sc = ssc[cl], sh = ssh[cl];
        float v0 = fmaxf(fmaf(r0.x, sc, sh), 0.f) + fmaxf(fmaf(r0.y, sc, sh), 0.f)
                 + fmaxf(fmaf(r1.x, sc, sh), 0.f) + fmaxf(fmaf(r1.y, sc, sh), 0.f);
        float v1 = fmaxf(fmaf(r0.z, sc, sh), 0.f) + fmaxf(fmaf(r0.w, sc, sh), 0.f)
                 + fmaxf(fmaf(r1.z, sc, sh), 0.f) + fmaxf(fmaf(r1.w, sc, sh), 0.f);
        sy[cl][2 * pr2]     = __float2half(v0 * 0.25f);
        sy[cl][2 * pr2 + 1] = __float2half(v1 * 0.25f);
    }
    __syncthreads();

    // phase B: write swizzled tile, coalesced rows
    const int kl = tid & 63;
    const int nb = tid >> 6;
    const uint32_t u   = (uint32_t)(kl >> 3);
    const uint32_t sub = (uint32_t)(kl & 7) * 2;
    char* base = (char*)g_yh + ((size_t)(c0 >> 6) * NBLK + (n0 >> 6)) * 8192;
#pragma unroll
    for (int ni = 0; ni < 16; ni++) {
        int nl2 = nb * 16 + ni;
        *(__half*)(base + (uint32_t)nl2 * 128
                   + ((u ^ (uint32_t)(nl2 & 7)) * 16) + sub) = sy[kl][nl2];
    }
}

// ============================================================================
// Kernel 2: fp16 GEMM via TMA bulk loads. BM=128 BN=64 BK=64, 8 chunks,
// 3-stage mbarrier ring, 3 CTAs/SM -> entire grid (392 CTAs) in ONE wave.
// ============================================================================
#define NCH     8
#define STG     3
#define A_BYTES 16384
#define B_BYTES 8192
#define STAGE_B 24576
#define MBAR_OFF (STG * STAGE_B)         // 73728
#define SMEM_TOT (MBAR_OFF + 64)

__global__ __launch_bounds__(256, 3) void gemm_mma(float* __restrict__ out) {
    extern __shared__ char smem[];
    const uint32_t sb = smem_u32(smem);
    const int tid = threadIdx.x;
    const int lid = tid & 31, wid = tid >> 5;
    const int nblk = blockIdx.x;
    const int mblk = blockIdx.y;
    const int n0 = nblk * 64;
    const int m0 = mblk * 128;

    if (tid == 0) {
#pragma unroll
        for (int s = 0; s < STG; s++) MBAR_INIT(sb + MBAR_OFF + s * 8, 1);
    }
    __syncthreads();

    auto issue = [&](int j) {
        const int slot = j % STG;
        const uint32_t s = sb + (uint32_t)slot * STAGE_B;
        const uint32_t mb = sb + MBAR_OFF + slot * 8;
        MBAR_EXPECT_TX(mb, STAGE_B);
        const char* aSrc = (const char*)g_wh + ((size_t)j * 2 + mblk) * A_BYTES;
        const char* bSrc = (const char*)g_yh + ((size_t)j * NBLK + nblk) * B_BYTES;
        BULK_G2S(s, aSrc, A_BYTES, mb);
        BULK_G2S(s + A_BYTES, bSrc, B_BYTES, mb);
    };

    if (tid == 0) { issue(0); issue(1); }

    // consumer mapping: 8 warps, tile 32m x 32n
    const int wm = wid & 3, wn = wid >> 2;
    const int half  = lid >> 4;
    const int bhalf = (lid >> 3) & 1;
    const int brow0 = wn * 32 + (lid & 7) + ((lid >> 4) << 3);
    const int brow1 = brow0 + 16;
    const int arow0 = wm * 32 + (lid & 15);

    float acc[2][4][4];
#pragma unroll
    for (int a = 0; a < 2; a++)
#pragma unroll
        for (int b = 0; b < 4; b++)
#pragma unroll
            for (int c = 0; c < 4; c++) acc[a][b][c] = 0.f;

    for (int i = 0; i < NCH; i++) {
        __syncthreads();                       // slot (i+2)%3 readers (chunk i-1) done
        if (tid == 0 && i + STG - 1 < NCH) issue(i + STG - 1);
        mbar_wait(sb + MBAR_OFF + (i % STG) * 8, (uint32_t)((i / STG) & 1));

        const uint32_t sA = sb + (uint32_t)(i % STG) * STAGE_B;
        const uint32_t sB = sA + A_BYTES;
#pragma unroll
        for (int ks = 0; ks < 4; ks++) {
            const uint32_t ub = (uint32_t)(2 * ks + bhalf);
            uint32_t b0, b1, b2, b3, b4, b5, b6, b7;
            LDSM4(b0, b1, b2, b3,
                  sB + (uint32_t)brow0 * 128 + ((ub ^ (uint32_t)(brow0 & 7)) * 16));
            LDSM4(b4, b5, b6, b7,
                  sB + (uint32_t)brow1 * 128 + ((ub ^ (uint32_t)(brow1 & 7)) * 16));
            const uint32_t ua = (uint32_t)(2 * ks + half);
#pragma unroll
            for (int mt = 0; mt < 2; mt++) {
                int rA = arow0 + mt * 16;
                uint32_t a0, a1, a2, a3;
                LDSM4(a0, a1, a2, a3,
                      sA + (uint32_t)rA * 128 + ((ua ^ (uint32_t)(rA & 7)) * 16));
                MMAF16(acc[mt][0], a0, a1, a2, a3, b0, b1);
                MMAF16(acc[mt][1], a0, a1, a2, a3, b2, b3);
                MMAF16(acc[mt][2], a0, a1, a2, a3, b4, b5);
                MMAF16(acc[mt][3], a0, a1, a2, a3, b6, b7);
            }
        }
    }

    // epilogue: direct float2 stores
#pragma unroll
    for (int mt = 0; mt < 2; mt++) {
#pragma unroll
        for (int nt = 0; nt < 4; nt++) {
            int m = m0 + wm * 32 + mt * 16 + (lid >> 2);
            int n = n0 + wn * 32 + nt * 8 + ((lid & 3) << 1);
            int b2 = n / NPB, p2 = n - b2 * NPB;
            float* o = out + ((size_t)b2 * COUT + m) * NPB + p2;
            *(float2*)o = make_float2(acc[mt][nt][0], acc[mt][nt][1]);
            *(float2*)(o + 8 * NPB) = make_float2(acc[mt][nt][2], acc[mt][nt][3]);
        }
    }
}

// ============================================================================
extern "C" void kernel_launch(void* const* d_in, const int* in_sizes, int n_in,
                              void* d_out, int out_size) {
    const float* x  = (const float*)d_in[0];
    const float* gw = (const float*)d_in[1];
    const float* gb = (const float*)d_in[2];
    const float* gm = (const float*)d_in[3];
    const float* gv = (const float*)d_in[4];
    const float* cw = (const float*)d_in[5];
    float* out = (float*)d_out;

    cudaFuncSetAttribute(gemm_mma, cudaFuncAttributeMaxDynamicSharedMemorySize, SMEM_TOT);

    fuse_pool<<<dim3(NBLK, 9), 256>>>(x, gw, gb, gm, gv, cw);
    gemm_mma<<<dim3(NBLK, 2), 256, SMEM_TOT>>>(out);
}